// round 13
// baseline (speedup 1.0000x reference)
#include <cuda_runtime.h>
#include <cstdint>
#include <math.h>

#define BB 4
#define SS 2048
#define DD 1024
#define HH 16
#define HDIM 64
#define MM (BB*SS)   /* 8192 */

// Scratch (device globals — no allocations allowed)
__device__ float g_Q [BB*SS*DD];
__device__ float g_K [BB*SS*DD];
__device__ float g_V [BB*SS*DD];
__device__ float g_AO[BB*SS*DD];

// ---------------------------------------------------------------------------
// tf32 helpers (plain PTX ISA — no sm_103a-gated features)
// ---------------------------------------------------------------------------
static __device__ __forceinline__ uint32_t f2tf(float x) {
    uint32_t u;
    asm("cvt.rna.tf32.f32 %0, %1;" : "=r"(u) : "f"(x));
    return u;
}

static __device__ __forceinline__ void mma8(float* c, const uint32_t* a,
                                            const uint32_t* b) {
    asm volatile(
        "mma.sync.aligned.m16n8k8.row.col.f32.tf32.tf32.f32 "
        "{%0,%1,%2,%3}, {%4,%5,%6,%7}, {%8,%9}, {%0,%1,%2,%3};"
        : "+f"(c[0]), "+f"(c[1]), "+f"(c[2]), "+f"(c[3])
        : "r"(a[0]), "r"(a[1]), "r"(a[2]), "r"(a[3]), "r"(b[0]), "r"(b[1]));
}

// ---------------------------------------------------------------------------
// tf32 mma.sync GEMM: C[M,N] = alpha * A[M,K] * W[N,K]^T (+ bias)
// CTA 128x128, 256 threads (8 warps x 32x64), K-chunk 32.
// Double-buffered smem, ONE barrier per chunk. gridDim.z selects problem.
// roundC!=0 -> output values are tf32-rounded (for downstream raw loads).
// ---------------------------------------------------------------------------
#define LDA 36
#define GSTG (128 * LDA)                 /* words per A (or W) buffer */
#define G_SMEM_BYTES (4 * GSTG * 4)      /* 2 stages x (A + W) = 73728 B */

__global__ __launch_bounds__(256) void gemm_mma(
    const float* __restrict__ A0, const float* __restrict__ W0, float* C0, float al0,
    const float* __restrict__ A1, const float* __restrict__ W1, float* C1, float al1,
    const float* __restrict__ A2, const float* __restrict__ W2, float* C2, float al2,
    const float* __restrict__ bias, int roundC)
{
    extern __shared__ uint32_t gsm[];

    const float* A; const float* W; float* C; float alpha;
    if (blockIdx.z == 0)      { A = A0; W = W0; C = C0; alpha = al0; }
    else if (blockIdx.z == 1) { A = A1; W = W1; C = C1; alpha = al1; }
    else                      { A = A2; W = W2; C = C2; alpha = al2; }

    const int tid  = threadIdx.x;
    const int w    = tid >> 5;
    const int lane = tid & 31;
    const int ly   = lane >> 2;
    const int lx   = lane & 3;
    const int m0   = blockIdx.y * 128;
    const int n0   = blockIdx.x * 128;
    const int wm   = (w & 3) * 32;
    const int wn   = (w >> 2) * 64;

    const int lrow = tid >> 3;
    const int lc4  = tid & 7;
    const float* Ap = A + (size_t)(m0 + lrow) * DD + lc4 * 4;
    const float* Wp = W + (size_t)(n0 + lrow) * DD + lc4 * 4;

    float acc[2][8][4];
#pragma unroll
    for (int i = 0; i < 2; i++)
#pragma unroll
        for (int j = 0; j < 8; j++)
#pragma unroll
            for (int r = 0; r < 4; r++) acc[i][j][r] = 0.f;

    float4 ra[4], rw[4];
#pragma unroll
    for (int i = 0; i < 4; i++) {                      // chunk 0 -> regs
        ra[i] = *(const float4*)(Ap + (size_t)(32 * i) * DD);
        rw[i] = *(const float4*)(Wp + (size_t)(32 * i) * DD);
    }
    {
        uint32_t* Ab = gsm;                            // buf 0
        uint32_t* Wb = gsm + GSTG;
#pragma unroll
        for (int i = 0; i < 4; i++) {
            uint32_t* pa = &Ab[(lrow + 32 * i) * LDA + lc4 * 4];
            pa[0] = f2tf(ra[i].x); pa[1] = f2tf(ra[i].y);
            pa[2] = f2tf(ra[i].z); pa[3] = f2tf(ra[i].w);
            uint32_t* pw = &Wb[(lrow + 32 * i) * LDA + lc4 * 4];
            pw[0] = f2tf(rw[i].x); pw[1] = f2tf(rw[i].y);
            pw[2] = f2tf(rw[i].z); pw[3] = f2tf(rw[i].w);
        }
    }
    __syncthreads();

    for (int kc = 0; kc < DD / 32; kc++) {
        uint32_t* Ab = gsm + (kc & 1) * 2 * GSTG;
        uint32_t* Wb = Ab + GSTG;

        if (kc + 1 < DD / 32) {                        // LDG next chunk
            const float* Ap2 = Ap + (kc + 1) * 32;
            const float* Wp2 = Wp + (kc + 1) * 32;
#pragma unroll
            for (int i = 0; i < 4; i++) {
                ra[i] = *(const float4*)(Ap2 + (size_t)(32 * i) * DD);
                rw[i] = *(const float4*)(Wp2 + (size_t)(32 * i) * DD);
            }
        }

#pragma unroll
        for (int ks = 0; ks < 4; ks++) {
            const int k0 = ks * 8;
            uint32_t af[2][4], bf[8][2];
#pragma unroll
            for (int i = 0; i < 2; i++) {
                int base = (wm + i * 16 + ly) * LDA + k0 + lx;
                af[i][0] = Ab[base];
                af[i][1] = Ab[base + 8 * LDA];
                af[i][2] = Ab[base + 4];
                af[i][3] = Ab[base + 8 * LDA + 4];
            }
#pragma unroll
            for (int j = 0; j < 8; j++) {
                int base = (wn + j * 8 + ly) * LDA + k0 + lx;
                bf[j][0] = Wb[base];
                bf[j][1] = Wb[base + 4];
            }
#pragma unroll
            for (int i = 0; i < 2; i++)
#pragma unroll
                for (int j = 0; j < 8; j++)
                    mma8(acc[i][j], af[i], bf[j]);
        }

        if (kc + 1 < DD / 32) {                        // STS next chunk
            uint32_t* An = gsm + ((kc + 1) & 1) * 2 * GSTG;
            uint32_t* Wn = An + GSTG;
#pragma unroll
            for (int i = 0; i < 4; i++) {
                uint32_t* pa = &An[(lrow + 32 * i) * LDA + lc4 * 4];
                pa[0] = f2tf(ra[i].x); pa[1] = f2tf(ra[i].y);
                pa[2] = f2tf(ra[i].z); pa[3] = f2tf(ra[i].w);
                uint32_t* pw = &Wn[(lrow + 32 * i) * LDA + lc4 * 4];
                pw[0] = f2tf(rw[i].x); pw[1] = f2tf(rw[i].y);
                pw[2] = f2tf(rw[i].z); pw[3] = f2tf(rw[i].w);
            }
        }
        __syncthreads();                               // single barrier
    }

#pragma unroll
    for (int i = 0; i < 2; i++) {
        int row = m0 + wm + i * 16 + ly;
#pragma unroll
        for (int j = 0; j < 8; j++) {
            int col = n0 + wn + j * 8 + lx * 2;
            float b0 = bias ? bias[col]     : 0.f;
            float b1 = bias ? bias[col + 1] : 0.f;
            float v0 = acc[i][j][0] * alpha + b0;
            float v1 = acc[i][j][1] * alpha + b1;
            float v2 = acc[i][j][2] * alpha + b0;
            float v3 = acc[i][j][3] * alpha + b1;
            if (roundC) {                 // pre-round for downstream tf32 use
                v0 = __uint_as_float(f2tf(v0));
                v1 = __uint_as_float(f2tf(v1));
                v2 = __uint_as_float(f2tf(v2));
                v3 = __uint_as_float(f2tf(v3));
            }
            *(float2*)(C + (size_t)row * DD + col)       = make_float2(v0, v1);
            *(float2*)(C + (size_t)(row + 8) * DD + col) = make_float2(v2, v3);
        }
    }
}

// ---------------------------------------------------------------------------
// Flash-attention, tf32 mma.sync, 2x query blocking, NO P smem round-trip.
// Trick: softmax output regs s{0,2,1,3} ARE a valid PV A-fragment if V's
// b-fragments take keys in order (2lx, 2lx+1) within each 8-key slice —
// softmax is key-permutation-invariant, so we permute V row addressing
// instead of relaying P through smem. Q/K/V arrive pre-rounded to tf32.
// smem: Ks stride 76, Vs stride 68 (2*68 % 32 == 8 -> conflict-free).
// ---------------------------------------------------------------------------
#define KST 76
#define VST 68

__global__ __launch_bounds__(128) void attn_mma(
    const float* __restrict__ Q,
    const float* __restrict__ K,
    const float* __restrict__ V,
    float* __restrict__ O)
{
    __shared__ uint32_t Ks[64 * KST];   // 19456 B
    __shared__ uint32_t Vs[64 * VST];   // 17408 B

    const int tid  = threadIdx.x;
    const int w    = tid >> 5;
    const int lane = tid & 31;
    const int ly   = lane >> 2;         // 0..7
    const int lx   = lane & 3;          // 0..3
    const int qw   = w * 32;            // warp query offset in 128-tile
    const int qt   = blockIdx.x;        // 0..15
    const int bh   = blockIdx.y;        // 0..63
    const int b    = bh >> 4;
    const int h    = bh & 15;

    const float* Qg = Q + ((size_t)b * SS + qt * 128) * DD + h * HDIM;
    const float* Kg = K + (size_t)b * SS * DD + h * HDIM;
    const float* Vg = V + (size_t)b * SS * DD + h * HDIM;
    float*       Og = O + ((size_t)b * SS + qt * 128) * DD + h * HDIM;

    // ---- Q fragments: raw bits (already tf32-rounded by the projection)
    uint32_t aq[2][8][4];
#pragma unroll
    for (int u = 0; u < 2; u++)
#pragma unroll
        for (int ks = 0; ks < 8; ks++) {
            const float* qp = Qg + (size_t)(qw + 16 * u + ly) * DD + ks * 8 + lx;
            aq[u][ks][0] = __float_as_uint(qp[0]);
            aq[u][ks][1] = __float_as_uint(qp[(size_t)8 * DD]);
            aq[u][ks][2] = __float_as_uint(qp[4]);
            aq[u][ks][3] = __float_as_uint(qp[(size_t)8 * DD + 4]);
        }

    float o[2][8][4];
    float m[2][2], l[2][2];
#pragma unroll
    for (int u = 0; u < 2; u++) {
        m[u][0] = m[u][1] = -1e30f;
        l[u][0] = l[u][1] = 0.f;
#pragma unroll
        for (int j = 0; j < 8; j++)
#pragma unroll
            for (int r = 0; r < 4; r++) o[u][j][r] = 0.f;
    }

    for (int t = 0; t < SS / 64; t++) {
        // ---- load K,V tiles (pre-rounded: plain bit-copy, no cvt)
#pragma unroll
        for (int it = 0; it < 8; it++) {
            int idx = it * 128 + tid;
            int c = idx >> 4, d4 = (idx & 15) << 2;
            float4 kv = *(const float4*)(Kg + (size_t)(t * 64 + c) * DD + d4);
            *(float4*)(Ks + c * KST + d4) = kv;
            float4 vv = *(const float4*)(Vg + (size_t)(t * 64 + c) * DD + d4);
            *(float4*)(Vs + c * VST + d4) = vv;
        }
        __syncthreads();

        // ---- S = Q K^T : each b-fragment feeds both query sets
        float s[2][8][4];
#pragma unroll
        for (int u = 0; u < 2; u++)
#pragma unroll
            for (int j = 0; j < 8; j++)
#pragma unroll
                for (int r = 0; r < 4; r++) s[u][j][r] = 0.f;

#pragma unroll
        for (int ks = 0; ks < 8; ks++) {
#pragma unroll
            for (int j = 0; j < 8; j++) {
                uint32_t bf[2];
                int base = (ly + 8 * j) * KST + 8 * ks + lx;
                bf[0] = Ks[base];
                bf[1] = Ks[base + 4];
                mma8(s[0][j], aq[0][ks], bf);
                mma8(s[1][j], aq[1][ks], bf);
            }
        }

        // ---- online softmax per query set (all in registers)
#pragma unroll
        for (int u = 0; u < 2; u++) {
            float mx0 = -1e30f, mx1 = -1e30f;
#pragma unroll
            for (int j = 0; j < 8; j++) {
                mx0 = fmaxf(mx0, fmaxf(s[u][j][0], s[u][j][1]));
                mx1 = fmaxf(mx1, fmaxf(s[u][j][2], s[u][j][3]));
            }
            mx0 = fmaxf(mx0, __shfl_xor_sync(0xffffffffu, mx0, 1));
            mx0 = fmaxf(mx0, __shfl_xor_sync(0xffffffffu, mx0, 2));
            mx1 = fmaxf(mx1, __shfl_xor_sync(0xffffffffu, mx1, 1));
            mx1 = fmaxf(mx1, __shfl_xor_sync(0xffffffffu, mx1, 2));
            float nm0 = fmaxf(m[u][0], mx0), nm1 = fmaxf(m[u][1], mx1);
            float c0 = __expf(m[u][0] - nm0), c1 = __expf(m[u][1] - nm1);
            m[u][0] = nm0; m[u][1] = nm1;
            float rs0 = 0.f, rs1 = 0.f;
#pragma unroll
            for (int j = 0; j < 8; j++) {
                s[u][j][0] = __expf(s[u][j][0] - nm0);
                s[u][j][1] = __expf(s[u][j][1] - nm0);
                s[u][j][2] = __expf(s[u][j][2] - nm1);
                s[u][j][3] = __expf(s[u][j][3] - nm1);
                rs0 += s[u][j][0] + s[u][j][1];
                rs1 += s[u][j][2] + s[u][j][3];
            }
            rs0 += __shfl_xor_sync(0xffffffffu, rs0, 1);
            rs0 += __shfl_xor_sync(0xffffffffu, rs0, 2);
            rs1 += __shfl_xor_sync(0xffffffffu, rs1, 1);
            rs1 += __shfl_xor_sync(0xffffffffu, rs1, 2);
            l[u][0] = l[u][0] * c0 + rs0;
            l[u][1] = l[u][1] * c1 + rs1;
#pragma unroll
            for (int j = 0; j < 8; j++) {
                o[u][j][0] *= c0; o[u][j][1] *= c0;
                o[u][j][2] *= c1; o[u][j][3] *= c1;
            }
        }

        // ---- O += P V : P A-fragments come straight from s registers.
        // Key order within each 8-key slice is (2lx, 2lx+1); V b-fragments
        // use the matching permuted rows. No P store/reload.
#pragma unroll
        for (int ks = 0; ks < 8; ks++) {
            uint32_t pa0[4], pa1[4];
            pa0[0] = f2tf(s[0][ks][0]); pa0[1] = f2tf(s[0][ks][2]);
            pa0[2] = f2tf(s[0][ks][1]); pa0[3] = f2tf(s[0][ks][3]);
            pa1[0] = f2tf(s[1][ks][0]); pa1[1] = f2tf(s[1][ks][2]);
            pa1[2] = f2tf(s[1][ks][1]); pa1[3] = f2tf(s[1][ks][3]);
#pragma unroll
            for (int j = 0; j < 8; j++) {
                uint32_t bf[2];
                int bb = (8 * ks + 2 * lx) * VST + ly + 8 * j;
                bf[0] = Vs[bb];            // key 8ks + 2lx
                bf[1] = Vs[bb + VST];      // key 8ks + 2lx + 1
                mma8(o[0][j], pa0, bf);
                mma8(o[1][j], pa1, bf);
            }
        }
        __syncthreads();   // all warps done with Ks/Vs before next tile load
    }

    // ---- normalize + write
#pragma unroll
    for (int u = 0; u < 2; u++) {
        float i0 = 1.f / l[u][0], i1 = 1.f / l[u][1];
        int r0 = qw + 16 * u + ly;
#pragma unroll
        for (int j = 0; j < 8; j++) {
            *(float2*)(Og + (size_t)r0 * DD + 8 * j + 2 * lx) =
                make_float2(o[u][j][0] * i0, o[u][j][1] * i0);
            *(float2*)(Og + (size_t)(r0 + 8) * DD + 8 * j + 2 * lx) =
                make_float2(o[u][j][2] * i1, o[u][j][3] * i1);
        }
    }
}

// ---------------------------------------------------------------------------
extern "C" void kernel_launch(void* const* d_in, const int* in_sizes, int n_in,
                              void* d_out, int out_size)
{
    const float* q  = (const float*)d_in[0];
    const float* k  = (const float*)d_in[1];
    const float* v  = (const float*)d_in[2];
    const float* Wq = (const float*)d_in[3];
    const float* Wk = (const float*)d_in[4];
    const float* Wv = (const float*)d_in[5];
    const float* Wo = (const float*)d_in[6];
    const float* bo = (const float*)d_in[7];
    float* out = (float*)d_out;

    void *pQ, *pK, *pV, *pAO;
    cudaGetSymbolAddress(&pQ,  g_Q);
    cudaGetSymbolAddress(&pK,  g_K);
    cudaGetSymbolAddress(&pV,  g_V);
    cudaGetSymbolAddress(&pAO, g_AO);

    cudaFuncSetAttribute(gemm_mma, cudaFuncAttributeMaxDynamicSharedMemorySize,
                         G_SMEM_BYTES);

    // fused Q/K/V projections (scale 1/32 folded into Q); outputs tf32-rounded
    dim3 gg3(DD / 128, MM / 128, 3);
    gemm_mma<<<gg3, 256, G_SMEM_BYTES>>>(q, Wq, (float*)pQ, 0.03125f,
                                         k, Wk, (float*)pK, 1.0f,
                                         v, Wv, (float*)pV, 1.0f, nullptr, 1);

    dim3 ga(SS / 128, BB * HH);    // (16, 64)
    attn_mma<<<ga, 128>>>((const float*)pQ, (const float*)pK,
                          (const float*)pV, (float*)pAO);

    dim3 gg(DD / 128, MM / 128, 1);
    gemm_mma<<<gg, 256, G_SMEM_BYTES>>>((const float*)pAO, Wo, out, 1.0f,
                                        nullptr, nullptr, nullptr, 0.f,
                                        nullptr, nullptr, nullptr, 0.f, bo, 0);
}

// round 14
// speedup vs baseline: 1.8110x; 1.8110x over previous
#include <cuda_runtime.h>
#include <cstdint>
#include <math.h>

#define BB 4
#define SS 2048
#define DD 1024
#define HH 16
#define HDIM 64
#define MM (BB*SS)   /* 8192 */

// Scratch (device globals — no allocations allowed)
__device__ float g_Q [BB*SS*DD];
__device__ float g_K [BB*SS*DD];
__device__ float g_V [BB*SS*DD];
__device__ float g_AO[BB*SS*DD];

// ---------------------------------------------------------------------------
// tf32 helpers (plain PTX ISA — no sm_103a-gated features)
// ---------------------------------------------------------------------------
static __device__ __forceinline__ uint32_t f2tf(float x) {
    uint32_t u;
    asm("cvt.rna.tf32.f32 %0, %1;" : "=r"(u) : "f"(x));
    return u;
}

static __device__ __forceinline__ void mma8(float* c, const uint32_t* a,
                                            const uint32_t* b) {
    asm volatile(
        "mma.sync.aligned.m16n8k8.row.col.f32.tf32.tf32.f32 "
        "{%0,%1,%2,%3}, {%4,%5,%6,%7}, {%8,%9}, {%0,%1,%2,%3};"
        : "+f"(c[0]), "+f"(c[1]), "+f"(c[2]), "+f"(c[3])
        : "r"(a[0]), "r"(a[1]), "r"(a[2]), "r"(a[3]), "r"(b[0]), "r"(b[1]));
}

// ---------------------------------------------------------------------------
// tf32 mma.sync GEMM (round-12 proven shape): C = alpha * A * W^T (+ bias).
// CTA 128x128, 256 threads (8 warps x 32x64), K-chunk 32, STATIC single-
// buffer smem (36 KB -> 2 CTAs/SM), register prefetch, 2 barriers/chunk.
// gridDim.z selects among up to 3 fused problems. roundC -> tf32-round C.
// ---------------------------------------------------------------------------
#define LDA 36

__global__ __launch_bounds__(256) void gemm_mma(
    const float* __restrict__ A0, const float* __restrict__ W0, float* C0, float al0,
    const float* __restrict__ A1, const float* __restrict__ W1, float* C1, float al1,
    const float* __restrict__ A2, const float* __restrict__ W2, float* C2, float al2,
    const float* __restrict__ bias, int roundC)
{
    __shared__ uint32_t As[128 * LDA];
    __shared__ uint32_t Ws[128 * LDA];

    const float* A; const float* W; float* C; float alpha;
    if (blockIdx.z == 0)      { A = A0; W = W0; C = C0; alpha = al0; }
    else if (blockIdx.z == 1) { A = A1; W = W1; C = C1; alpha = al1; }
    else                      { A = A2; W = W2; C = C2; alpha = al2; }

    const int tid  = threadIdx.x;
    const int w    = tid >> 5;
    const int lane = tid & 31;
    const int ly   = lane >> 2;
    const int lx   = lane & 3;
    const int m0   = blockIdx.y * 128;
    const int n0   = blockIdx.x * 128;
    const int wm   = (w & 3) * 32;
    const int wn   = (w >> 2) * 64;

    const int lrow = tid >> 3;
    const int lc4  = tid & 7;
    const float* Ap = A + (size_t)(m0 + lrow) * DD + lc4 * 4;
    const float* Wp = W + (size_t)(n0 + lrow) * DD + lc4 * 4;

    float acc[2][8][4];
#pragma unroll
    for (int i = 0; i < 2; i++)
#pragma unroll
        for (int j = 0; j < 8; j++)
#pragma unroll
            for (int r = 0; r < 4; r++) acc[i][j][r] = 0.f;

    float4 ra[4], rw[4];
#pragma unroll
    for (int i = 0; i < 4; i++) {
        ra[i] = *(const float4*)(Ap + (size_t)(32 * i) * DD);
        rw[i] = *(const float4*)(Wp + (size_t)(32 * i) * DD);
    }
#pragma unroll
    for (int i = 0; i < 4; i++) {
        uint32_t* pa = &As[(lrow + 32 * i) * LDA + lc4 * 4];
        pa[0] = f2tf(ra[i].x); pa[1] = f2tf(ra[i].y);
        pa[2] = f2tf(ra[i].z); pa[3] = f2tf(ra[i].w);
        uint32_t* pw = &Ws[(lrow + 32 * i) * LDA + lc4 * 4];
        pw[0] = f2tf(rw[i].x); pw[1] = f2tf(rw[i].y);
        pw[2] = f2tf(rw[i].z); pw[3] = f2tf(rw[i].w);
    }
    __syncthreads();

    for (int kc = 0; kc < DD / 32; kc++) {
        if (kc + 1 < DD / 32) {
            const float* Ap2 = Ap + (kc + 1) * 32;
            const float* Wp2 = Wp + (kc + 1) * 32;
#pragma unroll
            for (int i = 0; i < 4; i++) {
                ra[i] = *(const float4*)(Ap2 + (size_t)(32 * i) * DD);
                rw[i] = *(const float4*)(Wp2 + (size_t)(32 * i) * DD);
            }
        }

#pragma unroll
        for (int ks = 0; ks < 4; ks++) {
            const int k0 = ks * 8;
            uint32_t af[2][4], bf[8][2];
#pragma unroll
            for (int i = 0; i < 2; i++) {
                int base = (wm + i * 16 + ly) * LDA + k0 + lx;
                af[i][0] = As[base];
                af[i][1] = As[base + 8 * LDA];
                af[i][2] = As[base + 4];
                af[i][3] = As[base + 8 * LDA + 4];
            }
#pragma unroll
            for (int j = 0; j < 8; j++) {
                int base = (wn + j * 8 + ly) * LDA + k0 + lx;
                bf[j][0] = Ws[base];
                bf[j][1] = Ws[base + 4];
            }
#pragma unroll
            for (int i = 0; i < 2; i++)
#pragma unroll
                for (int j = 0; j < 8; j++)
                    mma8(acc[i][j], af[i], bf[j]);
        }
        __syncthreads();

        if (kc + 1 < DD / 32) {
#pragma unroll
            for (int i = 0; i < 4; i++) {
                uint32_t* pa = &As[(lrow + 32 * i) * LDA + lc4 * 4];
                pa[0] = f2tf(ra[i].x); pa[1] = f2tf(ra[i].y);
                pa[2] = f2tf(ra[i].z); pa[3] = f2tf(ra[i].w);
                uint32_t* pw = &Ws[(lrow + 32 * i) * LDA + lc4 * 4];
                pw[0] = f2tf(rw[i].x); pw[1] = f2tf(rw[i].y);
                pw[2] = f2tf(rw[i].z); pw[3] = f2tf(rw[i].w);
            }
            __syncthreads();
        }
    }

#pragma unroll
    for (int i = 0; i < 2; i++) {
        int row = m0 + wm + i * 16 + ly;
#pragma unroll
        for (int j = 0; j < 8; j++) {
            int col = n0 + wn + j * 8 + lx * 2;
            float b0 = bias ? bias[col]     : 0.f;
            float b1 = bias ? bias[col + 1] : 0.f;
            float v0 = acc[i][j][0] * alpha + b0;
            float v1 = acc[i][j][1] * alpha + b1;
            float v2 = acc[i][j][2] * alpha + b0;
            float v3 = acc[i][j][3] * alpha + b1;
            if (roundC) {                 // pre-round for downstream tf32 use
                v0 = __uint_as_float(f2tf(v0));
                v1 = __uint_as_float(f2tf(v1));
                v2 = __uint_as_float(f2tf(v2));
                v3 = __uint_as_float(f2tf(v3));
            }
            *(float2*)(C + (size_t)row * DD + col)       = make_float2(v0, v1);
            *(float2*)(C + (size_t)(row + 8) * DD + col) = make_float2(v2, v3);
        }
    }
}

// ---------------------------------------------------------------------------
// Flash-attention, tf32 mma.sync, 2x query blocking, no P smem round-trip.
// Register-pressure fix vs round 13: 64-key tiles are processed as two
// 32-key halves, so the score block is s[2][4][4] (32 regs) instead of 64.
// Peak live ~ aq(64)+o(64)+s(32) ≈ 170 regs -> no spills.
// P trick: softmax regs {s0,s2,s1,s3} ARE the PV A-fragment if V rows are
// taken in key order (2lx, 2lx+1) per 8-key slice (permutation-invariant).
// Q/K/V arrive pre-rounded to tf32 (raw bit loads, no cvt).
// ---------------------------------------------------------------------------
#define KST 76
#define VST 68

__global__ __launch_bounds__(128) void attn_mma(
    const float* __restrict__ Q,
    const float* __restrict__ K,
    const float* __restrict__ V,
    float* __restrict__ O)
{
    __shared__ uint32_t Ks[64 * KST];   // 19456 B
    __shared__ uint32_t Vs[64 * VST];   // 17408 B

    const int tid  = threadIdx.x;
    const int w    = tid >> 5;
    const int lane = tid & 31;
    const int ly   = lane >> 2;         // 0..7
    const int lx   = lane & 3;          // 0..3
    const int qw   = w * 32;            // warp query offset in 128-tile
    const int qt   = blockIdx.x;        // 0..15
    const int bh   = blockIdx.y;        // 0..63
    const int b    = bh >> 4;
    const int h    = bh & 15;

    const float* Qg = Q + ((size_t)b * SS + qt * 128) * DD + h * HDIM;
    const float* Kg = K + (size_t)b * SS * DD + h * HDIM;
    const float* Vg = V + (size_t)b * SS * DD + h * HDIM;
    float*       Og = O + ((size_t)b * SS + qt * 128) * DD + h * HDIM;

    // ---- Q fragments: raw bits (already tf32-rounded by the projection)
    uint32_t aq[2][8][4];
#pragma unroll
    for (int u = 0; u < 2; u++)
#pragma unroll
        for (int ks = 0; ks < 8; ks++) {
            const float* qp = Qg + (size_t)(qw + 16 * u + ly) * DD + ks * 8 + lx;
            aq[u][ks][0] = __float_as_uint(qp[0]);
            aq[u][ks][1] = __float_as_uint(qp[(size_t)8 * DD]);
            aq[u][ks][2] = __float_as_uint(qp[4]);
            aq[u][ks][3] = __float_as_uint(qp[(size_t)8 * DD + 4]);
        }

    float o[2][8][4];
    float m[2][2], l[2][2];
#pragma unroll
    for (int u = 0; u < 2; u++) {
        m[u][0] = m[u][1] = -1e30f;
        l[u][0] = l[u][1] = 0.f;
#pragma unroll
        for (int j = 0; j < 8; j++)
#pragma unroll
            for (int r = 0; r < 4; r++) o[u][j][r] = 0.f;
    }

    for (int t = 0; t < SS / 64; t++) {
        // ---- load K,V tiles (64 keys x 64 dims; raw bit copy)
#pragma unroll
        for (int it = 0; it < 8; it++) {
            int idx = it * 128 + tid;
            int c = idx >> 4, d4 = (idx & 15) << 2;
            *(float4*)(Ks + c * KST + d4) =
                *(const float4*)(Kg + (size_t)(t * 64 + c) * DD + d4);
            *(float4*)(Vs + c * VST + d4) =
                *(const float4*)(Vg + (size_t)(t * 64 + c) * DD + d4);
        }
        __syncthreads();

        // ---- process tile as two 32-key halves (caps live registers)
#pragma unroll
        for (int half = 0; half < 2; half++) {
            const int kb = half * 32;

            // S = Q K^T over this half's 32 keys
            float s[2][4][4];
#pragma unroll
            for (int u = 0; u < 2; u++)
#pragma unroll
                for (int j = 0; j < 4; j++)
#pragma unroll
                    for (int r = 0; r < 4; r++) s[u][j][r] = 0.f;

#pragma unroll
            for (int ks = 0; ks < 8; ks++) {
#pragma unroll
                for (int j = 0; j < 4; j++) {
                    uint32_t bf[2];
                    int base = (kb + ly + 8 * j) * KST + 8 * ks + lx;
                    bf[0] = Ks[base];
                    bf[1] = Ks[base + 4];
                    mma8(s[0][j], aq[0][ks], bf);
                    mma8(s[1][j], aq[1][ks], bf);
                }
            }

            // online softmax over these 32 keys
#pragma unroll
            for (int u = 0; u < 2; u++) {
                float mx0 = -1e30f, mx1 = -1e30f;
#pragma unroll
                for (int j = 0; j < 4; j++) {
                    mx0 = fmaxf(mx0, fmaxf(s[u][j][0], s[u][j][1]));
                    mx1 = fmaxf(mx1, fmaxf(s[u][j][2], s[u][j][3]));
                }
                mx0 = fmaxf(mx0, __shfl_xor_sync(0xffffffffu, mx0, 1));
                mx0 = fmaxf(mx0, __shfl_xor_sync(0xffffffffu, mx0, 2));
                mx1 = fmaxf(mx1, __shfl_xor_sync(0xffffffffu, mx1, 1));
                mx1 = fmaxf(mx1, __shfl_xor_sync(0xffffffffu, mx1, 2));
                float nm0 = fmaxf(m[u][0], mx0), nm1 = fmaxf(m[u][1], mx1);
                float c0 = __expf(m[u][0] - nm0), c1 = __expf(m[u][1] - nm1);
                m[u][0] = nm0; m[u][1] = nm1;
                float rs0 = 0.f, rs1 = 0.f;
#pragma unroll
                for (int j = 0; j < 4; j++) {
                    s[u][j][0] = __expf(s[u][j][0] - nm0);
                    s[u][j][1] = __expf(s[u][j][1] - nm0);
                    s[u][j][2] = __expf(s[u][j][2] - nm1);
                    s[u][j][3] = __expf(s[u][j][3] - nm1);
                    rs0 += s[u][j][0] + s[u][j][1];
                    rs1 += s[u][j][2] + s[u][j][3];
                }
                rs0 += __shfl_xor_sync(0xffffffffu, rs0, 1);
                rs0 += __shfl_xor_sync(0xffffffffu, rs0, 2);
                rs1 += __shfl_xor_sync(0xffffffffu, rs1, 1);
                rs1 += __shfl_xor_sync(0xffffffffu, rs1, 2);
                l[u][0] = l[u][0] * c0 + rs0;
                l[u][1] = l[u][1] * c1 + rs1;
#pragma unroll
                for (int j = 0; j < 8; j++) {
                    o[u][j][0] *= c0; o[u][j][1] *= c0;
                    o[u][j][2] *= c1; o[u][j][3] *= c1;
                }
            }

            // O += P V : s regs become A-fragments (permuted key order)
#pragma unroll
            for (int ks = 0; ks < 4; ks++) {
                uint32_t pa0[4], pa1[4];
                pa0[0] = f2tf(s[0][ks][0]); pa0[1] = f2tf(s[0][ks][2]);
                pa0[2] = f2tf(s[0][ks][1]); pa0[3] = f2tf(s[0][ks][3]);
                pa1[0] = f2tf(s[1][ks][0]); pa1[1] = f2tf(s[1][ks][2]);
                pa1[2] = f2tf(s[1][ks][1]); pa1[3] = f2tf(s[1][ks][3]);
#pragma unroll
                for (int j = 0; j < 8; j++) {
                    uint32_t bf[2];
                    int bb = (kb + 8 * ks + 2 * lx) * VST + ly + 8 * j;
                    bf[0] = Vs[bb];            // key kb + 8ks + 2lx
                    bf[1] = Vs[bb + VST];      // key kb + 8ks + 2lx + 1
                    mma8(o[0][j], pa0, bf);
                    mma8(o[1][j], pa1, bf);
                }
            }
        }
        __syncthreads();   // all warps done with Ks/Vs before next tile load
    }

    // ---- normalize + write
#pragma unroll
    for (int u = 0; u < 2; u++) {
        float i0 = 1.f / l[u][0], i1 = 1.f / l[u][1];
        int r0 = qw + 16 * u + ly;
#pragma unroll
        for (int j = 0; j < 8; j++) {
            *(float2*)(Og + (size_t)r0 * DD + 8 * j + 2 * lx) =
                make_float2(o[u][j][0] * i0, o[u][j][1] * i0);
            *(float2*)(Og + (size_t)(r0 + 8) * DD + 8 * j + 2 * lx) =
                make_float2(o[u][j][2] * i1, o[u][j][3] * i1);
        }
    }
}

// ---------------------------------------------------------------------------
extern "C" void kernel_launch(void* const* d_in, const int* in_sizes, int n_in,
                              void* d_out, int out_size)
{
    const float* q  = (const float*)d_in[0];
    const float* k  = (const float*)d_in[1];
    const float* v  = (const float*)d_in[2];
    const float* Wq = (const float*)d_in[3];
    const float* Wk = (const float*)d_in[4];
    const float* Wv = (const float*)d_in[5];
    const float* Wo = (const float*)d_in[6];
    const float* bo = (const float*)d_in[7];
    float* out = (float*)d_out;

    void *pQ, *pK, *pV, *pAO;
    cudaGetSymbolAddress(&pQ,  g_Q);
    cudaGetSymbolAddress(&pK,  g_K);
    cudaGetSymbolAddress(&pV,  g_V);
    cudaGetSymbolAddress(&pAO, g_AO);

    // fused Q/K/V projections (scale 1/32 folded into Q); outputs tf32-rounded
    dim3 gg3(DD / 128, MM / 128, 3);
    gemm_mma<<<gg3, 256>>>(q, Wq, (float*)pQ, 0.03125f,
                           k, Wk, (float*)pK, 1.0f,
                           v, Wv, (float*)pV, 1.0f, nullptr, 1);

    dim3 ga(SS / 128, BB * HH);    // (16, 64)
    attn_mma<<<ga, 128>>>((const float*)pQ, (const float*)pK,
                          (const float*)pV, (float*)pAO);

    dim3 gg(DD / 128, MM / 128, 1);
    gemm_mma<<<gg, 256>>>((const float*)pAO, Wo, out, 1.0f,
                          nullptr, nullptr, nullptr, 0.f,
                          nullptr, nullptr, nullptr, 0.f, bo, 0);
}